// round 16
// baseline (speedup 1.0000x reference)
#include <cuda_runtime.h>
#include <cstdint>
#include <math.h>

#define TA    512          // threads for scan kernels
#define TC    256          // threads for finish kernel
#define MAXB  256
#define CAPR  2048
#define TOPK  50
#define TOPP  0.9f
#define LOG2E 1.4426950408889634f

// ---------------- global scratch (no allocations allowed) ----------------
__device__ float g_partZ[2 * MAXB];
__device__ float g_warpTop[MAXB * 64];     // per row: 2 CTAs x 16 warps x top-2
__device__ int   g_candCnt[MAXB];
__device__ float g_candVal[MAXB * CAPR];
__device__ int   g_candIdx[MAXB * CAPR];

__device__ __forceinline__ float ex2(float x) {
    float r;
    asm("ex2.approx.f32 %0, %1;" : "=f"(r) : "f"(x));
    return r;
}

__device__ __forceinline__ uint32_t rotl_(uint32_t x, int r) { return (x << r) | (x >> (32 - r)); }

// ---------- JAX threefry2x32 (exact, 20 rounds) ----------
__device__ __forceinline__ void threefry2x32(uint32_t k0, uint32_t k1,
                                             uint32_t x0, uint32_t x1,
                                             uint32_t& o0, uint32_t& o1) {
    uint32_t k2 = k0 ^ k1 ^ 0x1BD11BDAu;
    x0 += k0; x1 += k1;
#define TFR(r) { x0 += x1; x1 = rotl_(x1, (r)); x1 ^= x0; }
    TFR(13) TFR(15) TFR(26) TFR(6)   x0 += k1; x1 += k2 + 1u;
    TFR(17) TFR(29) TFR(16) TFR(24)  x0 += k2; x1 += k0 + 2u;
    TFR(13) TFR(15) TFR(26) TFR(6)   x0 += k0; x1 += k1 + 3u;
    TFR(17) TFR(29) TFR(16) TFR(24)  x0 += k1; x1 += k2 + 4u;
    TFR(13) TFR(15) TFR(26) TFR(6)   x0 += k2; x1 += k0 + 5u;
#undef TFR
    o0 = x0; o1 = x1;
}

// jax.random.exponential(fold_in(key(0),1)) noise, partitionable path
__device__ __forceinline__ float jax_exp_noise(long long flat) {
    uint32_t fk0, fk1;
    threefry2x32(0u, 0u, 0u, 1u, fk0, fk1);
    uint32_t hi = (uint32_t)((unsigned long long)flat >> 32);
    uint32_t lo = (uint32_t)flat;
    uint32_t o0, o1;
    threefry2x32(fk0, fk1, hi, lo, o0, o1);
    uint32_t bits = o0 ^ o1;
    float u = __uint_as_float((bits >> 9) | 0x3f800000u) - 1.0f;
    return fmaxf(-log1pf(-u), 1e-10f);
}

// =================== K1: DRAM pass — partial Z + per-warp top-2 ===================
__global__ __launch_bounds__(TA)
void k1_scan(const float* __restrict__ logits, const float* __restrict__ temps, int V)
{
    const int bid = blockIdx.x;
    const int row = bid >> 1, h = bid & 1;
    const int tid = threadIdx.x, lane = tid & 31, wid = tid >> 5;

    __shared__ float redZ[16];

    const float C  = (1.0f / temps[row]) * LOG2E;
    const float* x = logits + (long long)row * V;
    const int Vh   = (V >> 1) & ~3;           // 16B-aligned split point
    const int beg  = h ? Vh : 0;
    const int end  = h ? V  : Vh;
    const int i0   = beg >> 2;
    const int i1   = end >> 2;                // float4 range [i0, i1)
    const float4* x4 = (const float4*)x;

    float z0 = 0.f, z1 = 0.f, z2 = 0.f, z3 = 0.f;
    float mx1 = -1e30f, mx2 = -1e30f;

#define K1_BODY(v)                                                          \
    {                                                                       \
        z0 += ex2((v).x * C); z1 += ex2((v).y * C);                         \
        z2 += ex2((v).z * C); z3 += ex2((v).w * C);                         \
        float g = fmaxf(fmaxf((v).x, (v).y), fmaxf((v).z, (v).w));          \
        mx2 = fmaxf(mx2, fminf(mx1, g)); mx1 = fmaxf(mx1, g);               \
    }

    int i = i0 + tid;
    for (; i + 7 * TA < i1; i += 8 * TA) {
        float4 v0 = x4[i];
        float4 v1 = x4[i + 1 * TA];
        float4 v2 = x4[i + 2 * TA];
        float4 v3 = x4[i + 3 * TA];
        float4 v4 = x4[i + 4 * TA];
        float4 v5 = x4[i + 5 * TA];
        float4 v6 = x4[i + 6 * TA];
        float4 v7 = x4[i + 7 * TA];
        K1_BODY(v0) K1_BODY(v1) K1_BODY(v2) K1_BODY(v3)
        K1_BODY(v4) K1_BODY(v5) K1_BODY(v6) K1_BODY(v7)
    }
    for (; i < i1; i += TA) {
        float4 v = x4[i];
        K1_BODY(v)
    }
    for (int t = (i1 << 2) + tid; t < end; t += TA) {   // scalar tail
        float xv = x[t];
        z0 += ex2(xv * C);
        mx2 = fmaxf(mx2, fminf(mx1, xv)); mx1 = fmaxf(mx1, xv);
    }
#undef K1_BODY

    float zsum = (z0 + z1) + (z2 + z3);
#pragma unroll
    for (int off = 16; off; off >>= 1) zsum += __shfl_xor_sync(0xffffffffu, zsum, off);
    if (lane == 0) redZ[wid] = zsum;

    // per-warp top-2 (values are genuine elements: per-float4 group maxes, disjoint groups)
    float w1 = mx1;
#pragma unroll
    for (int off = 16; off; off >>= 1) w1 = fmaxf(w1, __shfl_xor_sync(0xffffffffu, w1, off));
    unsigned mm = __ballot_sync(0xffffffffu, mx1 == w1);
    int leader  = __ffs(mm) - 1;
    float c2 = (lane == leader) ? mx2 : mx1;
    float w2 = c2;
#pragma unroll
    for (int off = 16; off; off >>= 1) w2 = fmaxf(w2, __shfl_xor_sync(0xffffffffu, w2, off));
    if (lane == 0) {
        g_warpTop[row * 64 + h * 32 + wid * 2]     = w1;
        g_warpTop[row * 64 + h * 32 + wid * 2 + 1] = w2;
    }
    __syncthreads();

    if (wid == 0) {
        float zz = (lane < 16) ? redZ[lane] : 0.0f;
#pragma unroll
        for (int off = 8; off; off >>= 1) zz += __shfl_xor_sync(0xffffffffu, zz, off);
        if (lane == 0) g_partZ[bid] = zz;
    }
    if (tid == 0) g_candCnt[row] = 0;   // reset for K2 (both halves write 0; benign)
}

// =================== K2: L2 pass — pivot + candidate gather ===================
__global__ __launch_bounds__(TA)
void k2_gather(const float* __restrict__ logits, int V)
{
    const int bid = blockIdx.x;
    const int row = bid >> 1, h = bid & 1;
    const int tid = threadIdx.x, lane = tid & 31, wid = tid >> 5;

    __shared__ float sPivot;

    // pivot = rank-(TOPK-1) among the row's 64 warp-top-2 values (all genuine elements,
    // min of any 50 distinct elements <= true 50th-largest)
    if (wid == 0) {
        const float* wt = &g_warpTop[row * 64];
        for (int e = lane; e < 64; e += 32) {
            float kv = wt[e];
            int r = 0;
            for (int t = 0; t < 64; t++) {
                float kt = wt[t];
                r += (kt > kv) || (kt == kv && t < e);
            }
            if (r == (TOPK - 1)) sPivot = kv;
        }
    }
    __syncthreads();
    const float pv = sPivot;

    const float* x = logits + (long long)row * V;
    const int Vh   = (V >> 1) & ~3;
    const int beg  = h ? Vh : 0;
    const int end  = h ? V  : Vh;
    const int i0   = beg >> 2;
    const int i1   = end >> 2;
    const float4* x4 = (const float4*)x;

    float* cv = &g_candVal[row * CAPR];
    int*   ci = &g_candIdx[row * CAPR];

#define K2_BODY(v, base)                                                                     \
    {                                                                                        \
        float gm = fmaxf(fmaxf((v).x, (v).y), fmaxf((v).z, (v).w));                          \
        if (gm >= pv) {                                                                      \
            if ((v).x >= pv) { int p = atomicAdd(&g_candCnt[row], 1); if (p < CAPR) { cv[p] = (v).x; ci[p] = (base);     } } \
            if ((v).y >= pv) { int p = atomicAdd(&g_candCnt[row], 1); if (p < CAPR) { cv[p] = (v).y; ci[p] = (base) + 1; } } \
            if ((v).z >= pv) { int p = atomicAdd(&g_candCnt[row], 1); if (p < CAPR) { cv[p] = (v).z; ci[p] = (base) + 2; } } \
            if ((v).w >= pv) { int p = atomicAdd(&g_candCnt[row], 1); if (p < CAPR) { cv[p] = (v).w; ci[p] = (base) + 3; } } \
        }                                                                                    \
    }

    int i = i0 + tid;
    for (; i + 7 * TA < i1; i += 8 * TA) {
        float4 v0 = x4[i];
        float4 v1 = x4[i + 1 * TA];
        float4 v2 = x4[i + 2 * TA];
        float4 v3 = x4[i + 3 * TA];
        float4 v4 = x4[i + 4 * TA];
        float4 v5 = x4[i + 5 * TA];
        float4 v6 = x4[i + 6 * TA];
        float4 v7 = x4[i + 7 * TA];
        K2_BODY(v0, 4 * i)
        K2_BODY(v1, 4 * (i + 1 * TA))
        K2_BODY(v2, 4 * (i + 2 * TA))
        K2_BODY(v3, 4 * (i + 3 * TA))
        K2_BODY(v4, 4 * (i + 4 * TA))
        K2_BODY(v5, 4 * (i + 5 * TA))
        K2_BODY(v6, 4 * (i + 6 * TA))
        K2_BODY(v7, 4 * (i + 7 * TA))
    }
    for (; i < i1; i += TA) {
        float4 v = x4[i];
        K2_BODY(v, 4 * i)
    }
    for (int t = (i1 << 2) + tid; t < end; t += TA) {
        float xv = x[t];
        if (xv >= pv) { int p = atomicAdd(&g_candCnt[row], 1); if (p < CAPR) { cv[p] = xv; ci[p] = t; } }
    }
#undef K2_BODY
}

// =================== K3: rank + top-p + noise + argmax ===================
__global__ __launch_bounds__(TC)
void k3_finish(const float* __restrict__ temps, float* __restrict__ out, int V)
{
    const int row = blockIdx.x;
    const int tid = threadIdx.x;

    __shared__ float cv[CAPR];
    __shared__ int   ci[CAPR];
    __shared__ float srtV[TOPK];
    __shared__ int   srtIdx[TOPK];
    __shared__ float srtP[TOPK];
    __shared__ float srtScore[TOPK];
    __shared__ int   sm_m;

    if (tid < TOPK) { srtV[tid] = -1e30f; srtIdx[tid] = 0; srtP[tid] = 0.0f; srtScore[tid] = -1.0f; }

    int n = g_candCnt[row];
    if (n > CAPR) n = CAPR;
    for (int j = tid; j < n; j += TC) {
        cv[j] = g_candVal[row * CAPR + j];
        ci[j] = g_candIdx[row * CAPR + j];
    }
    __syncthreads();

    // exact ranking (value desc, index asc) -> sorted top-50 (n >= 50 guaranteed by pivot)
    for (int j = tid; j < n; j += TC) {
        float vj = cv[j]; int ij = ci[j];
        int r = 0;
        for (int t = 0; t < n; t++) {
            float vt = cv[t]; int it = ci[t];
            r += (vt > vj) || (vt == vj && it < ij);
        }
        if (r < TOPK) { srtV[r] = vj; srtIdx[r] = ij; }
    }
    __syncthreads();

    const float C = (1.0f / temps[row]) * LOG2E;

    // top-p cumsum -> kept count m
    if (tid == 0) {
        float Z = g_partZ[2 * row] + g_partZ[2 * row + 1];
        int Keff = (TOPK < n) ? TOPK : n;
        if (Keff < 1) Keff = 1;
        float cum = 0.0f;
        int m = 1;
        for (int r = 0; r < Keff; r++) {
            float p = exp2f(srtV[r] * C) / Z;
            srtP[r] = p;
            cum += p;
            if (r == 0)           m = 1;
            else if (cum <= TOPP) m = r + 1;
            else break;
        }
        sm_m = m;
    }
    __syncthreads();

    // argmax(p / exp_noise) over kept set
    int m = sm_m;
    if (tid < m) {
        long long flat = (long long)row * V + (long long)srtIdx[tid];
        srtScore[tid] = srtP[tid] / jax_exp_noise(flat);
    }
    __syncthreads();
    if (tid == 0) {
        float best  = srtScore[0];
        int bestIdx = srtIdx[0];
        for (int r = 1; r < m; r++) {
            float sc = srtScore[r]; int iv = srtIdx[r];
            if (sc > best || (sc == best && iv < bestIdx)) { best = sc; bestIdx = iv; }
        }
        out[row] = (float)bestIdx;   // token as float32 value
    }
}

extern "C" void kernel_launch(void* const* d_in, const int* in_sizes, int n_in,
                              void* d_out, int out_size) {
    // logits = largest input; temps = largest remaining input. d_in[2] never read.
    int li = 0;
    for (int i = 1; i < n_in; i++) if (in_sizes[i] > in_sizes[li]) li = i;
    int te = -1;
    for (int i = 0; i < n_in; i++) {
        if (i == li) continue;
        if (te < 0 || in_sizes[i] > in_sizes[te]) te = i;
    }
    if (te < 0) te = (li == 0) ? 1 : 0;

    const float* logits = (const float*)d_in[li];
    const float* temps  = (const float*)d_in[te];
    float*       out    = (float*)d_out;

    int B = in_sizes[te];
    if (B > MAXB) B = MAXB;
    int V = in_sizes[li] / B;

    k1_scan  <<<2 * B, TA>>>(logits, temps, V);
    k2_gather<<<2 * B, TA>>>(logits, V);
    k3_finish<<<B,     TC>>>(temps, out, V);
}

// round 17
// speedup vs baseline: 1.1288x; 1.1288x over previous
#include <cuda_runtime.h>
#include <cstdint>
#include <math.h>

#define TB    256          // block size for all kernels
#define SEGS  8            // CTAs per row in scan kernels
#define MAXB  256
#define CAPR  1024
#define TOPK  50
#define TOPP  0.9f
#define LOG2E 1.4426950408889634f

// ---------------- global scratch (allocation-free) ----------------
__device__ float g_partZ[MAXB * SEGS];
__device__ float g_warpTop[MAXB * 128];    // per row: 8 CTAs x 8 warps x top-2 (genuine elements)
__device__ float g_pivot[MAXB];
__device__ int   g_arrive[MAXB];           // zero-init; winner resets -> replay-safe
__device__ int   g_candCnt[MAXB];
__device__ float g_candVal[MAXB * CAPR];
__device__ int   g_candIdx[MAXB * CAPR];

__device__ __forceinline__ float ex2(float x) {
    float r;
    asm("ex2.approx.f32 %0, %1;" : "=f"(r) : "f"(x));
    return r;
}

__device__ __forceinline__ uint32_t rotl_(uint32_t x, int r) { return (x << r) | (x >> (32 - r)); }

// ---------- JAX threefry2x32 (exact, 20 rounds) ----------
__device__ __forceinline__ void threefry2x32(uint32_t k0, uint32_t k1,
                                             uint32_t x0, uint32_t x1,
                                             uint32_t& o0, uint32_t& o1) {
    uint32_t k2 = k0 ^ k1 ^ 0x1BD11BDAu;
    x0 += k0; x1 += k1;
#define TFR(r) { x0 += x1; x1 = rotl_(x1, (r)); x1 ^= x0; }
    TFR(13) TFR(15) TFR(26) TFR(6)   x0 += k1; x1 += k2 + 1u;
    TFR(17) TFR(29) TFR(16) TFR(24)  x0 += k2; x1 += k0 + 2u;
    TFR(13) TFR(15) TFR(26) TFR(6)   x0 += k0; x1 += k1 + 3u;
    TFR(17) TFR(29) TFR(16) TFR(24)  x0 += k1; x1 += k2 + 4u;
    TFR(13) TFR(15) TFR(26) TFR(6)   x0 += k2; x1 += k0 + 5u;
#undef TFR
    o0 = x0; o1 = x1;
}

// jax.random.exponential(fold_in(key(0),1)) noise, partitionable path (bits = o0 ^ o1)
__device__ __forceinline__ float jax_exp_noise(long long flat) {
    uint32_t fk0, fk1;
    threefry2x32(0u, 0u, 0u, 1u, fk0, fk1);
    uint32_t hi = (uint32_t)((unsigned long long)flat >> 32);
    uint32_t lo = (uint32_t)flat;
    uint32_t o0, o1;
    threefry2x32(fk0, fk1, hi, lo, o0, o1);
    uint32_t bits = o0 ^ o1;
    float u = __uint_as_float((bits >> 9) | 0x3f800000u) - 1.0f;
    return fmaxf(-log1pf(-u), 1e-10f);
}

// segment boundaries in elements, 16B-aligned
__device__ __forceinline__ int seg_beg(int V, int s) { return (int)(((long long)s * V / SEGS) & ~3ll); }

// =================== K1: DRAM pass — partial Z + per-warp top-2 + last-CTA pivot ===================
__global__ __launch_bounds__(TB)
void k1_scan(const float* __restrict__ logits, const float* __restrict__ temps, int V)
{
    const int bid = blockIdx.x;
    const int row = bid / SEGS, seg = bid % SEGS;
    const int tid = threadIdx.x, lane = tid & 31, wid = tid >> 5;

    __shared__ float redZ[8];
    __shared__ int   sLast;

    const float C  = (1.0f / temps[row]) * LOG2E;
    const float* x = logits + (long long)row * V;
    const int beg  = seg_beg(V, seg);
    const int end  = (seg == SEGS - 1) ? V : seg_beg(V, seg + 1);
    const int i0   = beg >> 2;
    const int i1   = end >> 2;
    const float4* x4 = (const float4*)x;

    float z0 = 0.f, z1 = 0.f, z2 = 0.f, z3 = 0.f;
    float mx1 = -1e30f, mx2 = -1e30f;

#define K1_BODY(v)                                                          \
    {                                                                       \
        z0 += ex2((v).x * C); z1 += ex2((v).y * C);                         \
        z2 += ex2((v).z * C); z3 += ex2((v).w * C);                         \
        float g = fmaxf(fmaxf((v).x, (v).y), fmaxf((v).z, (v).w));          \
        mx2 = fmaxf(mx2, fminf(mx1, g)); mx1 = fmaxf(mx1, g);               \
    }

    int i = i0 + tid;
    for (; i + 7 * TB < i1; i += 8 * TB) {
        float4 v0 = x4[i];
        float4 v1 = x4[i + 1 * TB];
        float4 v2 = x4[i + 2 * TB];
        float4 v3 = x4[i + 3 * TB];
        float4 v4 = x4[i + 4 * TB];
        float4 v5 = x4[i + 5 * TB];
        float4 v6 = x4[i + 6 * TB];
        float4 v7 = x4[i + 7 * TB];
        K1_BODY(v0) K1_BODY(v1) K1_BODY(v2) K1_BODY(v3)
        K1_BODY(v4) K1_BODY(v5) K1_BODY(v6) K1_BODY(v7)
    }
    for (; i < i1; i += TB) {
        float4 v = x4[i];
        K1_BODY(v)
    }
    for (int t = (i1 << 2) + tid; t < end; t += TB) {   // scalar tail (last seg only)
        float xv = x[t];
        z0 += ex2(xv * C);
        mx2 = fmaxf(mx2, fminf(mx1, xv)); mx1 = fmaxf(mx1, xv);
    }
#undef K1_BODY

    float zsum = (z0 + z1) + (z2 + z3);
#pragma unroll
    for (int off = 16; off; off >>= 1) zsum += __shfl_xor_sync(0xffffffffu, zsum, off);
    if (lane == 0) redZ[wid] = zsum;

    // per-warp top-2 (genuine distinct elements: per-float4 group maxes over disjoint groups)
    float w1 = mx1;
#pragma unroll
    for (int off = 16; off; off >>= 1) w1 = fmaxf(w1, __shfl_xor_sync(0xffffffffu, w1, off));
    unsigned mm = __ballot_sync(0xffffffffu, mx1 == w1);
    int leader  = __ffs(mm) - 1;
    float c2 = (lane == leader) ? mx2 : mx1;
    float w2 = c2;
#pragma unroll
    for (int off = 16; off; off >>= 1) w2 = fmaxf(w2, __shfl_xor_sync(0xffffffffu, w2, off));
    if (lane == 0) {
        g_warpTop[row * 128 + seg * 16 + wid * 2]     = w1;
        g_warpTop[row * 128 + seg * 16 + wid * 2 + 1] = w2;
    }
    __syncthreads();

    if (wid == 0) {
        float zz = (lane < 8) ? redZ[lane] : 0.0f;
#pragma unroll
        for (int off = 4; off; off >>= 1) zz += __shfl_xor_sync(0xffffffffu, zz, off);
        if (lane == 0) g_partZ[row * SEGS + seg] = zz;
    }

    // last-arriving CTA of this row computes the pivot (no extra kernel launch)
    if (tid == 0) {
        __threadfence();
        int prev = atomicAdd(&g_arrive[row], 1);
        sLast = (prev == SEGS - 1) ? 1 : 0;
    }
    __syncthreads();
    if (sLast) {
        __threadfence();   // acquire: make all CTAs' g_warpTop writes visible
        if (tid < 128) {
            const float* wt = &g_warpTop[row * 128];
            float kv = wt[tid];
            int r = 0;
            for (int t = 0; t < 128; t++) {
                float kt = wt[t];
                r += (kt > kv) || (kt == kv && t < tid);
            }
            if (r == (TOPK - 1)) g_pivot[row] = kv;   // rank-49 of 128 genuine elems <= s50
        }
        if (tid == 0) { g_candCnt[row] = 0; g_arrive[row] = 0; }   // replay-safe reset
    }
}

// =================== K2: L2 pass — candidate gather ===================
__global__ __launch_bounds__(TB)
void k2_gather(const float* __restrict__ logits, int V)
{
    const int bid = blockIdx.x;
    const int row = bid / SEGS, seg = bid % SEGS;
    const int tid = threadIdx.x;

    const float pv = g_pivot[row];
    const float* x = logits + (long long)row * V;
    const int beg  = seg_beg(V, seg);
    const int end  = (seg == SEGS - 1) ? V : seg_beg(V, seg + 1);
    const int i0   = beg >> 2;
    const int i1   = end >> 2;
    const float4* x4 = (const float4*)x;

    float* cv = &g_candVal[row * CAPR];
    int*   ci = &g_candIdx[row * CAPR];

#define K2_BODY(v, base)                                                                     \
    {                                                                                        \
        float gm = fmaxf(fmaxf((v).x, (v).y), fmaxf((v).z, (v).w));                          \
        if (gm >= pv) {                                                                      \
            if ((v).x >= pv) { int p = atomicAdd(&g_candCnt[row], 1); if (p < CAPR) { cv[p] = (v).x; ci[p] = (base);     } } \
            if ((v).y >= pv) { int p = atomicAdd(&g_candCnt[row], 1); if (p < CAPR) { cv[p] = (v).y; ci[p] = (base) + 1; } } \
            if ((v).z >= pv) { int p = atomicAdd(&g_candCnt[row], 1); if (p < CAPR) { cv[p] = (v).z; ci[p] = (base) + 2; } } \
            if ((v).w >= pv) { int p = atomicAdd(&g_candCnt[row], 1); if (p < CAPR) { cv[p] = (v).w; ci[p] = (base) + 3; } } \
        }                                                                                    \
    }

    int i = i0 + tid;
    for (; i + 3 * TB < i1; i += 4 * TB) {
        float4 v0 = x4[i];
        float4 v1 = x4[i + 1 * TB];
        float4 v2 = x4[i + 2 * TB];
        float4 v3 = x4[i + 3 * TB];
        K2_BODY(v0, 4 * i)
        K2_BODY(v1, 4 * (i + 1 * TB))
        K2_BODY(v2, 4 * (i + 2 * TB))
        K2_BODY(v3, 4 * (i + 3 * TB))
    }
    for (; i < i1; i += TB) {
        float4 v = x4[i];
        K2_BODY(v, 4 * i)
    }
    for (int t = (i1 << 2) + tid; t < end; t += TB) {
        float xv = x[t];
        if (xv >= pv) { int p = atomicAdd(&g_candCnt[row], 1); if (p < CAPR) { cv[p] = xv; ci[p] = t; } }
    }
#undef K2_BODY
}

// =================== K3: rank + top-p + noise + argmax ===================
__global__ __launch_bounds__(TB)
void k3_finish(const float* __restrict__ temps, float* __restrict__ out, int V)
{
    const int row = blockIdx.x;
    const int tid = threadIdx.x;

    __shared__ float cv[CAPR];
    __shared__ int   ci[CAPR];
    __shared__ float srtV[TOPK];
    __shared__ int   srtIdx[TOPK];
    __shared__ float srtP[TOPK];
    __shared__ float srtScore[TOPK];
    __shared__ int   sm_m;

    if (tid < TOPK) { srtV[tid] = -1e30f; srtIdx[tid] = 0; srtP[tid] = 0.0f; srtScore[tid] = -1.0f; }

    int n = g_candCnt[row];
    if (n > CAPR) n = CAPR;
    for (int j = tid; j < n; j += TB) {
        cv[j] = g_candVal[row * CAPR + j];
        ci[j] = g_candIdx[row * CAPR + j];
    }
    __syncthreads();

    // exact ranking (value desc, index asc) -> sorted top-50
    for (int j = tid; j < n; j += TB) {
        float vj = cv[j]; int ij = ci[j];
        int r = 0;
        for (int t = 0; t < n; t++) {
            float vt = cv[t]; int it = ci[t];
            r += (vt > vj) || (vt == vj && it < ij);
        }
        if (r < TOPK) { srtV[r] = vj; srtIdx[r] = ij; }
    }
    __syncthreads();

    const float C = (1.0f / temps[row]) * LOG2E;

    if (tid == 0) {
        float Z = 0.0f;
#pragma unroll
        for (int s = 0; s < SEGS; s++) Z += g_partZ[row * SEGS + s];
        int Keff = (TOPK < n) ? TOPK : n;
        if (Keff < 1) Keff = 1;
        float cum = 0.0f;
        int m = 1;
        for (int r = 0; r < Keff; r++) {
            float p = exp2f(srtV[r] * C) / Z;
            srtP[r] = p;
            cum += p;
            if (r == 0)           m = 1;
            else if (cum <= TOPP) m = r + 1;
            else break;
        }
        sm_m = m;
    }
    __syncthreads();

    int m = sm_m;
    if (tid < m) {
        long long flat = (long long)row * V + (long long)srtIdx[tid];
        srtScore[tid] = srtP[tid] / jax_exp_noise(flat);
    }
    __syncthreads();
    if (tid == 0) {
        float best  = srtScore[0];
        int bestIdx = srtIdx[0];
        for (int r = 1; r < m; r++) {
            float sc = srtScore[r]; int iv = srtIdx[r];
            if (sc > best || (sc == best && iv < bestIdx)) { best = sc; bestIdx = iv; }
        }
        out[row] = (float)bestIdx;   // token as float32 value
    }
}

extern "C" void kernel_launch(void* const* d_in, const int* in_sizes, int n_in,
                              void* d_out, int out_size) {
    // logits = largest input; temps = largest remaining input. d_in[2] never read.
    int li = 0;
    for (int i = 1; i < n_in; i++) if (in_sizes[i] > in_sizes[li]) li = i;
    int te = -1;
    for (int i = 0; i < n_in; i++) {
        if (i == li) continue;
        if (te < 0 || in_sizes[i] > in_sizes[te]) te = i;
    }
    if (te < 0) te = (li == 0) ? 1 : 0;

    const float* logits = (const float*)d_in[li];
    const float* temps  = (const float*)d_in[te];
    float*       out    = (float*)d_out;

    int B = in_sizes[te];
    if (B > MAXB) B = MAXB;
    int V = in_sizes[li] / B;

    k1_scan  <<<SEGS * B, TB>>>(logits, temps, V);
    k2_gather<<<SEGS * B, TB>>>(logits, V);
    k3_finish<<<B,        TB>>>(temps, out, V);
}